// round 13
// baseline (speedup 1.0000x reference)
#include <cuda_runtime.h>
#include <cuda_bf16.h>
#include <cuda_fp16.h>
#include <math.h>
#include <stdint.h>

// ---------------------------------------------------------------------------
// Model constants
// ---------------------------------------------------------------------------
#define B_      2
#define S_      2048
#define T_      (B_ * S_)        // 4096 tokens
#define DIM_    1024
#define NH_     16
#define HD_     64
#define NL_     4
#define HFF_    2816
#define VOCAB_  32000
#define DD_     (DIM_ * DIM_)
#define FD_     (HFF_ * DIM_)

// bf16 weight arena offsets; QKV fused [wq;wk;wv]/layer, W13 row-interleaved
#define OFF_QKV 0
#define OFF_WO  (NL_ * 3 * DD_)
#define OFF_W13 (OFF_WO + NL_ * DD_)
#define OFF_W2  (OFF_W13 + NL_ * 2 * FD_)
#define WBF_    (OFF_W2 + NL_ * FD_)
#define SZ_OW   (VOCAB_ * DIM_)

// ---------------------------------------------------------------------------
// Scratch
// ---------------------------------------------------------------------------
__device__ __align__(16) float    g_h  [T_ * DIM_];
__device__ __align__(16) uint16_t g_xn_h[T_ * DIM_], g_xn_l[T_ * DIM_];
__device__ __align__(16) uint16_t g_o_h [T_ * DIM_], g_o_l [T_ * DIM_];
__device__ __align__(16) uint16_t g_gg_h[T_ * HFF_], g_gg_l[T_ * HFF_];
__device__ __align__(16) uint16_t g_qp_h[T_ * DIM_], g_qp_l[T_ * DIM_];
__device__ __align__(16) uint16_t g_kp_h[T_ * DIM_], g_kp_l[T_ * DIM_];
__device__ __align__(16) uint16_t g_vp_h[T_ * DIM_], g_vp_l[T_ * DIM_];
__device__ __align__(16) uint16_t g_w_h[WBF_], g_w_l[WBF_];
__device__ __align__(16) uint16_t g_wf16[SZ_OW];
__device__ __align__(16) uint16_t g_xnf16[T_ * DIM_];

// ---------------------------------------------------------------------------
// helpers
// ---------------------------------------------------------------------------
__device__ __forceinline__ uint32_t pack_bf16(__nv_bfloat16 a, __nv_bfloat16 b) {
    return (uint32_t)__bfloat16_as_ushort(a) |
           ((uint32_t)__bfloat16_as_ushort(b) << 16);
}
__device__ __forceinline__ uint32_t pack2f(float a, float b) {
    return pack_bf16(__float2bfloat16(a), __float2bfloat16(b));
}
__device__ __forceinline__ uint32_t pack2f_lo(float a, float b) {
    float ha = __bfloat162float(__float2bfloat16(a));
    float hb = __bfloat162float(__float2bfloat16(b));
    return pack_bf16(__float2bfloat16(a - ha), __float2bfloat16(b - hb));
}
__device__ __forceinline__ uint32_t pack2h(float a, float b) {
    __half2 h = __floats2half2_rn(a, b);
    return *(uint32_t*)&h;
}
__device__ __forceinline__ void split4(float4 v, uint2& hi, uint2& lo) {
    hi.x = pack2f(v.x, v.y);    hi.y = pack2f(v.z, v.w);
    lo.x = pack2f_lo(v.x, v.y); lo.y = pack2f_lo(v.z, v.w);
}
__device__ __forceinline__ void mma_bf16(float* c, const uint32_t* a,
                                         uint32_t b0, uint32_t b1) {
    asm volatile(
        "mma.sync.aligned.m16n8k16.row.col.f32.bf16.bf16.f32 "
        "{%0,%1,%2,%3}, {%4,%5,%6,%7}, {%8,%9}, {%0,%1,%2,%3};"
        : "+f"(c[0]), "+f"(c[1]), "+f"(c[2]), "+f"(c[3])
        : "r"(a[0]), "r"(a[1]), "r"(a[2]), "r"(a[3]),
          "r"(b0), "r"(b1));
}
__device__ __forceinline__ void mma_f16(float* c, const uint32_t* a,
                                        uint32_t b0, uint32_t b1) {
    asm volatile(
        "mma.sync.aligned.m16n8k16.row.col.f32.f16.f16.f32 "
        "{%0,%1,%2,%3}, {%4,%5,%6,%7}, {%8,%9}, {%0,%1,%2,%3};"
        : "+f"(c[0]), "+f"(c[1]), "+f"(c[2]), "+f"(c[3])
        : "r"(a[0]), "r"(a[1]), "r"(a[2]), "r"(a[3]),
          "r"(b0), "r"(b1));
}
__device__ __forceinline__ void ldsm4(uint32_t& r0, uint32_t& r1,
                                      uint32_t& r2, uint32_t& r3, uint32_t addr) {
    asm volatile("ldmatrix.sync.aligned.m8n8.x4.shared.b16 {%0,%1,%2,%3}, [%4];"
        : "=r"(r0), "=r"(r1), "=r"(r2), "=r"(r3) : "r"(addr));
}
__device__ __forceinline__ void ldsm4t(uint32_t& r0, uint32_t& r1,
                                       uint32_t& r2, uint32_t& r3, uint32_t addr) {
    asm volatile("ldmatrix.sync.aligned.m8n8.x4.trans.shared.b16 {%0,%1,%2,%3}, [%4];"
        : "=r"(r0), "=r"(r1), "=r"(r2), "=r"(r3) : "r"(addr));
}
__device__ __forceinline__ void cp16(uint32_t dst, const void* src) {
    asm volatile("cp.async.cg.shared.global [%0], [%1], 16;"
                 :: "r"(dst), "l"(src) : "memory");
}
__device__ __forceinline__ void cp_commit() {
    asm volatile("cp.async.commit_group;" ::: "memory");
}
template<int N>
__device__ __forceinline__ void cp_wait() {
    asm volatile("cp.async.wait_group %0;" :: "n"(N) : "memory");
}

// ---------------------------------------------------------------------------
// Embedding gather
// ---------------------------------------------------------------------------
__global__ void embed_kernel(const int* __restrict__ tokens,
                             const float* __restrict__ emb,
                             float* __restrict__ h) {
    int t = blockIdx.x;
    int tok = tokens[t];
    const float* src = emb + (size_t)tok * DIM_;
    float* dst = h + (size_t)t * DIM_;
    for (int i = threadIdx.x; i < DIM_; i += blockDim.x) dst[i] = src[i];
}

// ---------------------------------------------------------------------------
// weight splits
// ---------------------------------------------------------------------------
__global__ void split_kernel(const float* __restrict__ src,
                             uint16_t* __restrict__ hi,
                             uint16_t* __restrict__ lo, int nquad) {
    int i = blockIdx.x * blockDim.x + threadIdx.x;
    if (i >= nquad) return;
    float4 v = *(const float4*)(src + 4 * (size_t)i);
    uint2 h, l;
    split4(v, h, l);
    *(uint2*)((uint32_t*)hi + 2 * (size_t)i) = h;
    *(uint2*)((uint32_t*)lo + 2 * (size_t)i) = l;
}

__global__ void split_qkv_kernel(const float* __restrict__ wq,
                                 const float* __restrict__ wk,
                                 const float* __restrict__ wv,
                                 uint16_t* __restrict__ hi,
                                 uint16_t* __restrict__ lo) {
    const int QL = 3 * DD_ / 4;
    const int QD = DD_ / 4;
    int i = blockIdx.x * blockDim.x + threadIdx.x;
    int l = i / QL;
    int rem = i - l * QL;
    int part = rem / QD;
    int j = rem - part * QD;
    const float* src = (part == 0 ? wq : part == 1 ? wk : wv) + (size_t)l * DD_ + 4 * (size_t)j;
    float4 v = *(const float4*)src;
    uint2 h, lw;
    split4(v, h, lw);
    *(uint2*)((uint32_t*)hi + 2 * (size_t)i) = h;
    *(uint2*)((uint32_t*)lo + 2 * (size_t)i) = lw;
}

// W13 arena ROW-INTERLEAVED: arena row 2f = w1 row f, row 2f+1 = w3 row f
__global__ void split_w13i_kernel(const float* __restrict__ w1,
                                  const float* __restrict__ w3,
                                  uint16_t* __restrict__ hi,
                                  uint16_t* __restrict__ lo) {
    const int QROW = DIM_ / 4;              // 256 quads per row
    const int QL = 2 * HFF_ * QROW;         // quads per layer
    int i = blockIdx.x * blockDim.x + threadIdx.x;
    int l = i / QL;
    int rem = i - l * QL;
    int r = rem / QROW;                     // interleaved row
    int j = rem - r * QROW;
    const float* src = ((r & 1) ? w3 : w1) + (size_t)l * FD_
                     + (size_t)(r >> 1) * DIM_ + 4 * (size_t)j;
    float4 v = *(const float4*)src;
    uint2 h, lw;
    split4(v, h, lw);
    *(uint2*)((uint32_t*)hi + 2 * (size_t)i) = h;
    *(uint2*)((uint32_t*)lo + 2 * (size_t)i) = lw;
}

__global__ void split_f16_kernel(const float* __restrict__ src,
                                 uint16_t* __restrict__ dst, int nquad) {
    int i = blockIdx.x * blockDim.x + threadIdx.x;
    if (i >= nquad) return;
    float4 v = *(const float4*)(src + 4 * (size_t)i);
    uint2 h;
    h.x = pack2h(v.x, v.y);
    h.y = pack2h(v.z, v.w);
    *(uint2*)((uint32_t*)dst + 2 * (size_t)i) = h;
}

// ---------------------------------------------------------------------------
// RMSNorm -> bf16 hi/lo planes  /  fp16 plane
// ---------------------------------------------------------------------------
__global__ void rmsnorm_split(const float* __restrict__ x,
                              const float* __restrict__ w,
                              uint16_t* __restrict__ yh,
                              uint16_t* __restrict__ yl) {
    int t = blockIdx.x;
    const float* xr = x + (size_t)t * DIM_;
    float ss = 0.f;
    #pragma unroll
    for (int i = threadIdx.x; i < DIM_; i += 256) { float v = xr[i]; ss += v * v; }
    #pragma unroll
    for (int off = 16; off > 0; off >>= 1)
        ss += __shfl_xor_sync(0xffffffffu, ss, off);
    __shared__ float red[8];
    if ((threadIdx.x & 31) == 0) red[threadIdx.x >> 5] = ss;
    __syncthreads();
    float tot = 0.f;
    #pragma unroll
    for (int i = 0; i < 8; i++) tot += red[i];
    float sc = rsqrtf(tot * (1.0f / DIM_) + 1e-5f);
    uint32_t* oh = (uint32_t*)(yh + (size_t)t * DIM_);
    uint32_t* ol = (uint32_t*)(yl + (size_t)t * DIM_);
    #pragma unroll
    for (int i = threadIdx.x * 2; i < DIM_; i += 512) {
        float a = xr[i] * sc * w[i];
        float b = xr[i + 1] * sc * w[i + 1];
        oh[i >> 1] = pack2f(a, b);
        ol[i >> 1] = pack2f_lo(a, b);
    }
}

__global__ void rmsnorm_f16(const float* __restrict__ x,
                            const float* __restrict__ w,
                            uint16_t* __restrict__ y) {
    int t = blockIdx.x;
    const float* xr = x + (size_t)t * DIM_;
    float ss = 0.f;
    #pragma unroll
    for (int i = threadIdx.x; i < DIM_; i += 256) { float v = xr[i]; ss += v * v; }
    #pragma unroll
    for (int off = 16; off > 0; off >>= 1)
        ss += __shfl_xor_sync(0xffffffffu, ss, off);
    __shared__ float red[8];
    if ((threadIdx.x & 31) == 0) red[threadIdx.x >> 5] = ss;
    __syncthreads();
    float tot = 0.f;
    #pragma unroll
    for (int i = 0; i < 8; i++) tot += red[i];
    float sc = rsqrtf(tot * (1.0f / DIM_) + 1e-5f);
    uint32_t* oy = (uint32_t*)(y + (size_t)t * DIM_);
    #pragma unroll
    for (int i = threadIdx.x * 2; i < DIM_; i += 512)
        oy[i >> 1] = pack2h(xr[i] * sc * w[i], xr[i + 1] * sc * w[i + 1]);
}

// ---------------------------------------------------------------------------
// Shared 3xBF16 GEMM mainloop (128x128 CTA, 4 warps 64x64, 4-stage pipeline).
// EPI selects the epilogue: 0 = fp32 C (optional ACC), 1 = QKV rope+split,
// 2 = W13 silu+split.
// ---------------------------------------------------------------------------
#define SW_   12
#define PLW_  (128 * SW_)
#define PLB_  (PLW_ * 4)
#define STGB_ (4 * PLB_)
#define GSM_  (4 * STGB_)

template<int EPI, bool ACC>
__global__ __launch_bounds__(128, 2)
void tgemm_bb(const uint16_t* __restrict__ Ah, const uint16_t* __restrict__ Al,
              const uint16_t* __restrict__ Bh, const uint16_t* __restrict__ Bl,
              float* __restrict__ C,
              uint16_t* __restrict__ P0h, uint16_t* __restrict__ P0l,
              uint16_t* __restrict__ P1h, uint16_t* __restrict__ P1l,
              uint16_t* __restrict__ P2h, uint16_t* __restrict__ P2l,
              int M, int N, int K) {
    extern __shared__ __align__(16) uint32_t sm[];

    int tid  = threadIdx.x;
    int m0   = blockIdx.y * 128;
    int n0   = blockIdx.x * 128;
    int wid  = tid >> 5;
    int lane = tid & 31;
    int wm = (wid >> 1) * 64;
    int wn = (wid & 1) * 64;
    int lr = lane >> 2;
    int lc = lane & 3;

    uint32_t smb = (uint32_t)__cvta_generic_to_shared(sm);

    uint32_t aoff[4];
    #pragma unroll
    for (int mf = 0; mf < 4; mf++) {
        int row = wm + mf * 16 + (lane & 7) + ((lane >> 3) & 1) * 8;
        aoff[mf] = row * (SW_ * 4) + (lane >> 4) * 16;
    }
    uint32_t boff[4];
    #pragma unroll
    for (int nfp = 0; nfp < 4; nfp++) {
        int row = wn + nfp * 16 + (lane & 7) + (lane >> 4) * 8;
        boff[nfp] = row * (SW_ * 4) + ((lane >> 3) & 1) * 16;
    }

    int r0 = tid >> 1, h0 = tid & 1;
    int c1 = tid + 128;
    int r1 = c1 >> 1, h1 = c1 & 1;
    uint32_t sd0 = r0 * (SW_ * 4) + h0 * 16;
    uint32_t sd1 = r1 * (SW_ * 4) + h1 * 16;
    size_t ga0 = (size_t)(m0 + r0) * K + h0 * 8;
    size_t ga1 = (size_t)(m0 + r1) * K + h1 * 8;
    size_t gb0 = (size_t)(n0 + r0) * K + h0 * 8;
    size_t gb1 = (size_t)(n0 + r1) * K + h1 * 8;

    auto issue = [&](int bi, int k0) {
        uint32_t sb = smb + (uint32_t)bi * STGB_;
        cp16(sb + 0 * PLB_ + sd0, Ah + ga0 + k0);
        cp16(sb + 0 * PLB_ + sd1, Ah + ga1 + k0);
        cp16(sb + 1 * PLB_ + sd0, Al + ga0 + k0);
        cp16(sb + 1 * PLB_ + sd1, Al + ga1 + k0);
        cp16(sb + 2 * PLB_ + sd0, Bh + gb0 + k0);
        cp16(sb + 2 * PLB_ + sd1, Bh + gb1 + k0);
        cp16(sb + 3 * PLB_ + sd0, Bl + gb0 + k0);
        cp16(sb + 3 * PLB_ + sd1, Bl + gb1 + k0);
        cp_commit();
    };

    float acc[4][8][4];
    #pragma unroll
    for (int i = 0; i < 4; i++)
        #pragma unroll
        for (int j = 0; j < 8; j++)
            #pragma unroll
            for (int t = 0; t < 4; t++) acc[i][j][t] = 0.f;

    int nstage = K >> 4;
    issue(0, 0);
    if (nstage > 1) issue(1, 16);
    if (nstage > 2) issue(2, 32);

    for (int s = 0; s < nstage; s++) {
        int rem = nstage - 1 - s;
        if (rem >= 2)      cp_wait<2>();
        else if (rem == 1) cp_wait<1>();
        else               cp_wait<0>();
        __syncthreads();

        uint32_t bb = smb + (uint32_t)(s & 3) * STGB_;
        uint32_t ah[4][4], al[4][4];
        #pragma unroll
        for (int mf = 0; mf < 4; mf++) {
            ldsm4(ah[mf][0], ah[mf][1], ah[mf][2], ah[mf][3], bb + aoff[mf]);
            ldsm4(al[mf][0], al[mf][1], al[mf][2], al[mf][3], bb + PLB_ + aoff[mf]);
        }
        #pragma unroll
        for (int g = 0; g < 2; g++) {
            uint32_t bh[2][4], bl[2][4];
            #pragma unroll
            for (int p = 0; p < 2; p++) {
                int nfp = g * 2 + p;
                ldsm4(bh[p][0], bh[p][1], bh[p][2], bh[p][3],
                      bb + 2 * PLB_ + boff[nfp]);
                ldsm4(bl[p][0], bl[p][1], bl[p][2], bl[p][3],
                      bb + 3 * PLB_ + boff[nfp]);
            }
            #pragma unroll
            for (int p = 0; p < 2; p++) {
                int nf0 = (g * 2 + p) * 2, nf1 = nf0 + 1;
                #pragma unroll
                for (int mf = 0; mf < 4; mf++) {
                    mma_bf16(acc[mf][nf0], al[mf], bh[p][0], bh[p][1]);
                    mma_bf16(acc[mf][nf1], al[mf], bh[p][2], bh[p][3]);
                }
            }
            #pragma unroll
            for (int p = 0; p < 2; p++) {
                int nf0 = (g * 2 + p) * 2, nf1 = nf0 + 1;
                #pragma unroll
                for (int mf = 0; mf < 4; mf++) {
                    mma_bf16(acc[mf][nf0], ah[mf], bl[p][0], bl[p][1]);
                    mma_bf16(acc[mf][nf1], ah[mf], bl[p][2], bl[p][3]);
                }
            }
            #pragma unroll
            for (int p = 0; p < 2; p++) {
                int nf0 = (g * 2 + p) * 2, nf1 = nf0 + 1;
                #pragma unroll
                for (int mf = 0; mf < 4; mf++) {
                    mma_bf16(acc[mf][nf0], ah[mf], bh[p][0], bh[p][1]);
                    mma_bf16(acc[mf][nf1], ah[mf], bh[p][2], bh[p][3]);
                }
            }
        }

        int ns = s + 3;
        if (ns < nstage) issue(ns & 3, ns * 16);
    }

    // ---------------- epilogues ----------------
    if (EPI == 0) {
        #pragma unroll
        for (int mf = 0; mf < 4; mf++) {
            #pragma unroll
            for (int nf = 0; nf < 8; nf++) {
                int row = m0 + wm + mf * 16 + lr;
                int col = n0 + wn + nf * 8 + 2 * lc;
                float* p0 = C + (size_t)row * N + col;
                float* p1 = p0 + (size_t)8 * N;
                if (ACC) {
                    float2 u0 = *(float2*)p0;
                    float2 u1 = *(float2*)p1;
                    u0.x += acc[mf][nf][0]; u0.y += acc[mf][nf][1];
                    u1.x += acc[mf][nf][2]; u1.y += acc[mf][nf][3];
                    *(float2*)p0 = u0;
                    *(float2*)p1 = u1;
                } else {
                    *(float2*)p0 = make_float2(acc[mf][nf][0], acc[mf][nf][1]);
                    *(float2*)p1 = make_float2(acc[mf][nf][2], acc[mf][nf][3]);
                }
            }
        }
    } else if (EPI == 1) {
        // QKV: rope (q,k) + split to planes; q pre-scaled 1/8. col pairs are
        // rope pairs (2p, 2p+1). Section constant per warp (64-col range).
        int sec = (n0 + wn) >> 10;                   // 0=q 1=k 2=v
        uint16_t* Dh = sec == 0 ? P0h : sec == 1 ? P1h : P2h;
        uint16_t* Dl = sec == 0 ? P0l : sec == 1 ? P1l : P2l;
        #pragma unroll
        for (int mf = 0; mf < 4; mf++) {
            int row = m0 + wm + mf * 16 + lr;
            #pragma unroll
            for (int nf = 0; nf < 8; nf++) {
                int col = n0 + wn + nf * 8 + 2 * lc;
                int d = col & 1023;
                int p = d >> 1;
                float x0 = acc[mf][nf][0], x1 = acc[mf][nf][1];
                float y0 = acc[mf][nf][2], y1 = acc[mf][nf][3];
                if (sec < 2) {
                    int i_ = p & 31;
                    float inv = expf(-(float)(2 * i_) * (1.0f / HD_) * 9.210340371976184f);
                    float sn0, cs0, sn1, cs1;
                    sincosf((float)(row & (S_ - 1)) * inv, &sn0, &cs0);
                    sincosf((float)((row + 8) & (S_ - 1)) * inv, &sn1, &cs1);
                    float r00 = x0 * cs0 - x1 * sn0;
                    float r01 = x0 * sn0 + x1 * cs0;
                    float r10 = y0 * cs1 - y1 * sn1;
                    float r11 = y0 * sn1 + y1 * cs1;
                    if (sec == 0) {
                        r00 *= 0.125f; r01 *= 0.125f;
                        r10 *= 0.125f; r11 *= 0.125f;
                    }
                    x0 = r00; x1 = r01; y0 = r10; y1 = r11;
                }
                uint32_t w0 = (uint32_t)row * 512 + p;
                uint32_t w1 = w0 + 8 * 512;
                ((uint32_t*)Dh)[w0] = pack2f(x0, x1);
                ((uint32_t*)Dl)[w0] = pack2f_lo(x0, x1);
                ((uint32_t*)Dh)[w1] = pack2f(y0, y1);
                ((uint32_t*)Dl)[w1] = pack2f_lo(y0, y1);
            }
        }
    } else {
        // W13 (interleaved): col even = g1_f, col+1 = g3_f; gg = silu(g1)*g3
        #pragma unroll
        for (int mf = 0; mf < 4; mf++) {
            int row = m0 + wm + mf * 16 + lr;
            #pragma unroll
            for (int nf = 0; nf < 8; nf++) {
                int col = n0 + wn + nf * 8 + 2 * lc;
                int f = col >> 1;
                float a0 = acc[mf][nf][0], b0 = acc[mf][nf][1];
                float a1 = acc[mf][nf][2], b1 = acc[mf][nf][3];
                float gg0 = a0 / (1.f + __expf(-a0)) * b0;
                float gg1 = a1 / (1.f + __expf(-a1)) * b1;
                size_t e0 = (size_t)row * HFF_ + f;
                size_t e1 = e0 + (size_t)8 * HFF_;
                __nv_bfloat16 h0 = __float2bfloat16(gg0);
                __nv_bfloat16 h1 = __float2bfloat16(gg1);
                P0h[e0] = __bfloat16_as_ushort(h0);
                P0l[e0] = __bfloat16_as_ushort(__float2bfloat16(gg0 - __bfloat162float(h0)));
                P0h[e1] = __bfloat16_as_ushort(h1);
                P0l[e1] = __bfloat16_as_ushort(__float2bfloat16(gg1 - __bfloat162float(h1)));
            }
        }
    }
}

// ---------------------------------------------------------------------------
// fp16 single-pass GEMM NT (logits), 4 warps 64x64 warp tile
// ---------------------------------------------------------------------------
#define HSTGB_ (2 * PLB_)
#define HGSM_  (4 * HSTGB_)

__global__ __launch_bounds__(128, 2)
void tgemm_hh(const uint16_t* __restrict__ A, const uint16_t* __restrict__ B,
              float* __restrict__ C, int M, int N, int K) {
    extern __shared__ __align__(16) uint32_t sm[];

    int tid  = threadIdx.x;
    int m0   = blockIdx.y * 128;
    int n0   = blockIdx.x * 128;
    int wid  = tid >> 5;
    int lane = tid & 31;
    int wm = (wid >> 1) * 64;
    int wn = (wid & 1) * 64;
    int lr = lane >> 2;
    int lc = lane & 3;

    uint32_t smb = (uint32_t)__cvta_generic_to_shared(sm);

    uint32_t aoff[4];
    #pragma unroll
    for (int mf = 0; mf < 4; mf++) {
        int row = wm + mf * 16 + (lane & 7) + ((lane >> 3) & 1) * 8;
        aoff[mf] = row * (SW_ * 4) + (lane >> 4) * 16;
    }
    uint32_t boff[4];
    #pragma unroll
    for (int nfp = 0; nfp < 4; nfp++) {
        int row = wn + nfp * 16 + (lane & 7) + (lane >> 4) * 8;
        boff[nfp] = row * (SW_ * 4) + ((lane >> 3) & 1) * 16;
    }

    int r0 = tid >> 1, h0 = tid & 1;
    int c1 = tid + 128;
    int r1 = c1 >> 1, h1 = c1 & 1;
    uint32_t sd0 = r0 * (SW_ * 4) + h0 * 16;
    uint32_t sd1 = r1 * (SW_ * 4) + h1 * 16;
    size_t ga0 = (size_t)(m0 + r0) * K + h0 * 8;
    size_t ga1 = (size_t)(m0 + r1) * K + h1 * 8;
    size_t gb0 = (size_t)(n0 + r0) * K + h0 * 8;
    size_t gb1 = (size_t)(n0 + r1) * K + h1 * 8;

    auto issue = [&](int bi, int k0) {
        uint32_t sb = smb + (uint32_t)bi * HSTGB_;
        cp16(sb + sd0, A + ga0 + k0);
        cp16(sb + sd1, A + ga1 + k0);
        cp16(sb + PLB_ + sd0, B + gb0 + k0);
        cp16(sb + PLB_ + sd1, B + gb1 + k0);
        cp_commit();
    };

    float acc[4][8][4];
    #pragma unroll
    for (int i = 0; i < 4; i++)
        #pragma unroll
        for (int j = 0; j < 8; j++)
            #pragma unroll
            for (int t = 0; t < 4; t++) acc[i][j][t] = 0.f;

    int nstage = K >> 4;
    issue(0, 0);
    if (nstage > 1) issue(1, 16);
    if (nstage > 2) issue(2, 32);

    for (int s = 0; s < nstage; s++) {
        int rem = nstage - 1 - s;
        if (rem >= 2)      cp_wait<2>();
        else if (rem == 1) cp_wait<1>();
        else               cp_wait<0>();
        __syncthreads();

        uint32_t bb = smb + (uint32_t)(s & 3) * HSTGB_;
        uint32_t a[4][4];
        #pragma unroll
        for (int mf = 0; mf < 4; mf++)
            ldsm4(a[mf][0], a[mf][1], a[mf][2], a[mf][3], bb + aoff[mf]);
        #pragma unroll
        for (int nfp = 0; nfp < 4; nfp++) {
            uint32_t bh[4];
            ldsm4(bh[0], bh[1], bh[2], bh[3], bb + PLB_ + boff[nfp]);
            int nf0 = nfp * 2, nf1 = nf0 + 1;
            #pragma unroll
            for (int mf = 0; mf < 4; mf++) {
                mma_f16(acc[mf][nf0], a[mf], bh[0], bh[1]);
                mma_f16(acc[mf][nf1], a[mf], bh[2], bh[3]);
            }
        }

        int ns = s + 3;
        if (ns < nstage) issue(ns & 3, ns * 16);
    }

    #pragma unroll
    for (int mf = 0; mf < 4; mf++) {
        #pragma unroll
        for (int nf = 0; nf < 8; nf++) {
            int row = m0 + wm + mf * 16 + lr;
            int col = n0 + wn + nf * 8 + 2 * lc;
            float* p0 = C + (size_t)row * N + col;
            float* p1 = p0 + (size_t)8 * N;
            *(float2*)p0 = make_float2(acc[mf][nf][0], acc[mf][nf][1]);
            *(float2*)p1 = make_float2(acc[mf][nf][2], acc[mf][nf][3]);
        }
    }
}

// ---------------------------------------------------------------------------
// Tensor-core flash attention on pre-split bf16 planes (R10, proven)
// ---------------------------------------------------------------------------
#define APW_ 36
#define APLB_ (64 * APW_ * 4)

__global__ __launch_bounds__(128)
void attn_mma_kernel(const uint16_t* __restrict__ qh, const uint16_t* __restrict__ ql,
                     const uint16_t* __restrict__ kh, const uint16_t* __restrict__ kl,
                     const uint16_t* __restrict__ vh, const uint16_t* __restrict__ vl,
                     uint16_t* __restrict__ oh, uint16_t* __restrict__ ol) {
    __shared__ __align__(16) uint32_t sK[2][64 * APW_];
    __shared__ __align__(16) uint32_t sV[2][64 * APW_];

    int q0  = blockIdx.x * 64;
    int h   = blockIdx.y;
    int b   = blockIdx.z;
    int tid = threadIdx.x;
    int w   = tid >> 5;
    int lane = tid & 31;
    int lr = lane >> 2, lc = lane & 3;

    size_t base = ((size_t)b * S_) * DIM_ + (size_t)h * HD_;

    uint32_t sKb = (uint32_t)__cvta_generic_to_shared(&sK[0][0]);
    uint32_t sVb = (uint32_t)__cvta_generic_to_shared(&sV[0][0]);

    #pragma unroll
    for (int i = 0; i < 8; i++) {
        int idx = tid + i * 128;
        int row = idx >> 4, c4 = idx & 15;
        size_t e = base + (size_t)(q0 + row) * DIM_ + c4 * 4;
        uint32_t wofs = (uint32_t)(e >> 1);
        int wo = row * APW_ + c4 * 2;
        *(uint2*)&sK[0][wo] = *(const uint2*)((const uint32_t*)qh + wofs);
        *(uint2*)&sK[1][wo] = *(const uint2*)((const uint32_t*)ql + wofs);
    }
    __syncthreads();

    uint32_t Qh[4][4], Ql[4][4];
    {
        int arow = w * 16 + (lane & 7) + ((lane >> 3) & 1) * 8;
        uint32_t ab = arow * (APW_ * 4) + (lane >> 4) * 16;
        #pragma unroll
        for (int kc = 0; kc < 4; kc++) {
            ldsm4(Qh[kc][0], Qh[kc][1], Qh[kc][2], Qh[kc][3], sKb + ab + kc * 32);
            ldsm4(Ql[kc][0], Ql[kc][1], Ql[kc][2], Ql[kc][3], sKb + APLB_ + ab + kc * 32);
        }
    }

    uint32_t koff[4], voff[4][4];
    #pragma unroll
    for (int nfp = 0; nfp < 4; nfp++) {
        int row = nfp * 16 + (lane & 7) + (lane >> 4) * 8;
        koff[nfp] = row * (APW_ * 4) + ((lane >> 3) & 1) * 16;
        #pragma unroll
        for (int kc = 0; kc < 4; kc++) {
            int vrow = kc * 16 + ((lane >> 3) & 1) * 8 + (lane & 7);
            voff[nfp][kc] = vrow * (APW_ * 4) + (nfp * 2 + (lane >> 4)) * 16;
        }
    }

    float accO[8][4];
    #pragma unroll
    for (int nf = 0; nf < 8; nf++)
        #pragma unroll
        for (int t = 0; t < 4; t++) accO[nf][t] = 0.f;
    float m0 = -INFINITY, m1 = -INFINITY, l0 = 0.f, l1 = 0.f;

    int nkt = blockIdx.x + 1;
    for (int kt = 0; kt < nkt; kt++) {
        int k0 = kt * 64;
        __syncthreads();
        #pragma unroll
        for (int i = 0; i < 8; i++) {
            int idx = tid + i * 128;
            int row = idx >> 4, c4 = idx & 15;
            size_t e = base + (size_t)(k0 + row) * DIM_ + c4 * 4;
            uint32_t wofs = (uint32_t)(e >> 1);
            int wo = row * APW_ + c4 * 2;
            *(uint2*)&sK[0][wo] = *(const uint2*)((const uint32_t*)kh + wofs);
            *(uint2*)&sK[1][wo] = *(const uint2*)((const uint32_t*)kl + wofs);
            *(uint2*)&sV[0][wo] = *(const uint2*)((const uint32_t*)vh + wofs);
            *(uint2*)&sV[1][wo] = *(const uint2*)((const uint32_t*)vl + wofs);
        }
        __syncthreads();

        float sc[8][4];
        #pragma unroll
        for (int nf = 0; nf < 8; nf++)
            #pragma unroll
            for (int t = 0; t < 4; t++) sc[nf][t] = 0.f;

        #pragma unroll
        for (int nfp = 0; nfp < 4; nfp++) {
            #pragma unroll
            for (int kc = 0; kc < 4; kc++) {
                uint32_t bh[4], bl[4];
                ldsm4(bh[0], bh[1], bh[2], bh[3], sKb + koff[nfp] + kc * 32);
                ldsm4(bl[0], bl[1], bl[2], bl[3], sKb + APLB_ + koff[nfp] + kc * 32);
                int nf0 = nfp * 2, nf1 = nf0 + 1;
                mma_bf16(sc[nf0], Ql[kc], bh[0], bh[1]);
                mma_bf16(sc[nf0], Qh[kc], bl[0], bl[1]);
                mma_bf16(sc[nf0], Qh[kc], bh[0], bh[1]);
                mma_bf16(sc[nf1], Ql[kc], bh[2], bh[3]);
                mma_bf16(sc[nf1], Qh[kc], bl[2], bl[3]);
                mma_bf16(sc[nf1], Qh[kc], bh[2], bh[3]);
            }
        }

        if (kt == nkt - 1) {
            int row0 = w * 16 + lr;
            int row1 = row0 + 8;
            #pragma unroll
            for (int nf = 0; nf < 8; nf++) {
                int col = nf * 8 + 2 * lc;
                if (col     > row0) sc[nf][0] = -INFINITY;
                if (col + 1 > row0) sc[nf][1] = -INFINITY;
                if (col     > row1) sc[nf][2] = -INFINITY;
                if (col + 1 > row1) sc[nf][3] = -INFINITY;
            }
        }

        float tm0 = -INFINITY, tm1 = -INFINITY;
        #pragma unroll
        for (int nf = 0; nf < 8; nf++) {
            tm0 = fmaxf(tm0, fmaxf(sc[nf][0], sc[nf][1]));
            tm1 = fmaxf(tm1, fmaxf(sc[nf][2], sc[nf][3]));
        }
        #pragma unroll
        for (int off = 1; off < 4; off <<= 1) {
            tm0 = fmaxf(tm0, __shfl_xor_sync(0xffffffffu, tm0, off));
            tm1 = fmaxf(tm1, __shfl_xor_sync(0xffffffffu, tm1, off));
        }
        float mn0 = fmaxf(m0, tm0), mn1 = fmaxf(m1, tm1);
        float corr0 = __expf(m0 - mn0), corr1 = __expf(m1 - mn1);
        m0 = mn0; m1 = mn1;

        float ls0 = 0.f, ls1 = 0.f;
        #pragma unroll
        for (int nf = 0; nf < 8; nf++) {
            sc[nf][0] = __expf(sc[nf][0] - mn0);
            sc[nf][1] = __expf(sc[nf][1] - mn0);
            sc[nf][2] = __expf(sc[nf][2] - mn1);
            sc[nf][3] = __expf(sc[nf][3] - mn1);
            ls0 += sc[nf][0] + sc[nf][1];
            ls1 += sc[nf][2] + sc[nf][3];
        }
        #pragma unroll
        for (int off = 1; off < 4; off <<= 1) {
            ls0 += __shfl_xor_sync(0xffffffffu, ls0, off);
            ls1 += __shfl_xor_sync(0xffffffffu, ls1, off);
        }
        l0 = l0 * corr0 + ls0;
        l1 = l1 * corr1 + ls1;
        #pragma unroll
        for (int nf = 0; nf < 8; nf++) {
            accO[nf][0] *= corr0; accO[nf][1] *= corr0;
            accO[nf][2] *= corr1; accO[nf][3] *= corr1;
        }

        uint32_t Ph[4][4], Pl[4][4];
        #pragma unroll
        for (int kc = 0; kc < 4; kc++) {
            int na = 2 * kc, nb = 2 * kc + 1;
            Ph[kc][0] = pack2f(sc[na][0], sc[na][1]);
            Ph[kc][1] = pack2f(sc[na][2], sc[na][3]);
            Ph[kc][2] = pack2f(sc[nb][0], sc[nb][1]);
            Ph[kc][3] = pack2f(sc[nb][2], sc[nb][3]);
            Pl[kc][0] = pack2f_lo(sc[na][0], sc[na][1]);
            Pl[kc][1] = pack2f_lo(sc[na][2], sc[na][3]);
            Pl[kc][2] = pack2f_lo(sc[nb][0], sc[nb][1]);
            Pl[kc][3] = pack2f_lo(sc[nb][2], sc[nb][3]);
        }

        #pragma unroll
        for (int nfp = 0; nfp < 4; nfp++) {
            #pragma unroll
            for (int kc = 0; kc < 4; kc++) {
                uint32_t vhf[4], vlf[4];
                ldsm4t(vhf[0], vhf[1], vhf[2], vhf[3], sVb + voff[nfp][kc]);
                ldsm4t(vlf[0], vlf[1], vlf[2], vlf[3], sVb + APLB_ + voff[nfp][kc]);
                int nf0 = nfp * 2, nf1 = nf0 + 1;
                mma_bf16(accO[nf0], Pl[kc], vhf[0], vhf[1]);
                mma_bf16(accO[nf0], Ph[kc], vlf[0], vlf[1]);
                mma_bf16(accO[nf0], Ph[kc], vhf[0], vhf[1]);
                mma_bf16(accO[nf1], Pl[kc], vhf[2], vhf[3]);
                mma_bf16(accO[nf1], Ph[kc], vlf[2], vlf[3]);
                mma_bf16(accO[nf1], Ph[kc], vhf[2], vhf[3]);
            }
        }
    }

    float inv0 = 1.f / l0, inv1 = 1.f / l1;
    int row0 = q0 + w * 16 + lr;
    #pragma unroll
    for (int nf = 0; nf < 8; nf++) {
        int col = nf * 8 + 2 * lc;
        float x0 = accO[nf][0] * inv0, x1 = accO[nf][1] * inv0;
        float y0 = accO[nf][2] * inv1, y1 = accO[nf][3] * inv1;
        size_t e0 = base + (size_t)row0 * DIM_ + col;
        size_t e1 = base + (size_t)(row0 + 8) * DIM_ + col;
        *(uint32_t*)(oh + e0) = pack2f(x0, x1);
        *(uint32_t*)(ol + e0) = pack2f_lo(x0, x1);
        *(uint32_t*)(oh + e1) = pack2f(y0, y1);
        *(uint32_t*)(ol + e1) = pack2f_lo(y0, y1);
    }
}

// ---------------------------------------------------------------------------
// Host orchestration
// ---------------------------------------------------------------------------
extern "C" void kernel_launch(void* const* d_in, const int* in_sizes, int n_in,
                              void* d_out, int out_size) {
    const int*   tokens      = (const int*)  d_in[0];
    const float* tok_emb     = (const float*)d_in[1];
    const float* wq          = (const float*)d_in[2];
    const float* wk          = (const float*)d_in[3];
    const float* wv          = (const float*)d_in[4];
    const float* wo          = (const float*)d_in[5];
    const float* w1          = (const float*)d_in[6];
    const float* w2          = (const float*)d_in[7];
    const float* w3          = (const float*)d_in[8];
    const float* attn_norm_w = (const float*)d_in[9];
    const float* ffn_norm_w  = (const float*)d_in[10];
    const float* norm_w      = (const float*)d_in[11];
    const float* out_w       = (const float*)d_in[12];

    float *h;
    uint16_t *xnh, *xnl, *ooh, *ool, *ggh, *ggl, *wh, *wl, *wf16, *xnf;
    uint16_t *qph, *qpl, *kph, *kpl, *vph, *vpl;
    cudaGetSymbolAddress((void**)&h,    g_h);
    cudaGetSymbolAddress((void**)&xnh,  g_xn_h);
    cudaGetSymbolAddress((void**)&xnl,  g_xn_l);
    cudaGetSymbolAddress((void**)&ooh,  g_o_h);
    cudaGetSymbolAddress((void**)&ool,  g_o_l);
    cudaGetSymbolAddress((void**)&ggh,  g_gg_h);
    cudaGetSymbolAddress((void**)&ggl,  g_gg_l);
    cudaGetSymbolAddress((void**)&qph,  g_qp_h);
    cudaGetSymbolAddress((void**)&qpl,  g_qp_l);
    cudaGetSymbolAddress((void**)&kph,  g_kp_h);
    cudaGetSymbolAddress((void**)&kpl,  g_kp_l);
    cudaGetSymbolAddress((void**)&vph,  g_vp_h);
    cudaGetSymbolAddress((void**)&vpl,  g_vp_l);
    cudaGetSymbolAddress((void**)&wh,   g_w_h);
    cudaGetSymbolAddress((void**)&wl,   g_w_l);
    cudaGetSymbolAddress((void**)&wf16, g_wf16);
    cudaGetSymbolAddress((void**)&xnf,  g_xnf16);

    cudaFuncSetAttribute(tgemm_bb<0, false>, cudaFuncAttributeMaxDynamicSharedMemorySize, GSM_);
    cudaFuncSetAttribute(tgemm_bb<0, true >, cudaFuncAttributeMaxDynamicSharedMemorySize, GSM_);
    cudaFuncSetAttribute(tgemm_bb<1, false>, cudaFuncAttributeMaxDynamicSharedMemorySize, GSM_);
    cudaFuncSetAttribute(tgemm_bb<2, false>, cudaFuncAttributeMaxDynamicSharedMemorySize, GSM_);
    cudaFuncSetAttribute(tgemm_hh, cudaFuncAttributeMaxDynamicSharedMemorySize, HGSM_);

    // fused weight pre-splits (5 launches)
    {
        int nq = NL_ * 3 * DD_ / 4;
        split_qkv_kernel<<<nq / 256, 256>>>(wq, wk, wv, wh + OFF_QKV, wl + OFF_QKV);
    }
    {
        int nq = NL_ * 2 * FD_ / 4;
        split_w13i_kernel<<<nq / 256, 256>>>(w1, w3, wh + OFF_W13, wl + OFF_W13);
    }
    split_kernel<<<(NL_ * DD_ / 4) / 256, 256>>>(wo, wh + OFF_WO, wl + OFF_WO, NL_ * DD_ / 4);
    split_kernel<<<(NL_ * FD_ / 4) / 256, 256>>>(w2, wh + OFF_W2, wl + OFF_W2, NL_ * FD_ / 4);
    split_f16_kernel<<<(SZ_OW / 4) / 256, 256>>>(out_w, wf16, SZ_OW / 4);

    embed_kernel<<<T_, 256>>>(tokens, tok_emb, h);

    dim3 gQKV(3 * DIM_ / 128, T_ / 128);
    dim3 gDD (DIM_     / 128, T_ / 128);
    dim3 gF13(2 * HFF_ / 128, T_ / 128);
    dim3 gDV (VOCAB_   / 128, T_ / 128);

    for (int l = 0; l < NL_; l++) {
        size_t oQKV = OFF_QKV + (size_t)l * 3 * DD_;
        size_t oWO  = OFF_WO  + (size_t)l * DD_;
        size_t oW13 = OFF_W13 + (size_t)l * 2 * FD_;
        size_t oW2  = OFF_W2  + (size_t)l * FD_;

        rmsnorm_split<<<T_, 256>>>(h, attn_norm_w + (size_t)l * DIM_, xnh, xnl);
        tgemm_bb<1, false><<<gQKV, 128, GSM_>>>(xnh, xnl, wh + oQKV, wl + oQKV,
                                                nullptr,
                                                qph, qpl, kph, kpl, vph, vpl,
                                                T_, 3 * DIM_, DIM_);
        attn_mma_kernel<<<dim3(S_ / 64, NH_, B_), 128>>>(qph, qpl, kph, kpl, vph, vpl,
                                                         ooh, ool);
        tgemm_bb<0, true ><<<gDD, 128, GSM_>>>(ooh, ool, wh + oWO, wl + oWO,
                                               h, nullptr, nullptr, nullptr,
                                               nullptr, nullptr, nullptr,
                                               T_, DIM_, DIM_);

        rmsnorm_split<<<T_, 256>>>(h, ffn_norm_w + (size_t)l * DIM_, xnh, xnl);
        tgemm_bb<2, false><<<gF13, 128, GSM_>>>(xnh, xnl, wh + oW13, wl + oW13,
                                                nullptr,
                                                ggh, ggl, nullptr, nullptr,
                                                nullptr, nullptr,
                                                T_, 2 * HFF_, DIM_);
        tgemm_bb<0, true ><<<gDD, 128, GSM_>>>(ggh, ggl, wh + oW2, wl + oW2,
                                               h, nullptr, nullptr, nullptr,
                                               nullptr, nullptr, nullptr,
                                               T_, DIM_, HFF_);
    }

    rmsnorm_f16<<<T_, 256>>>(h, norm_w, xnf);
    tgemm_hh<<<gDV, 128, HGSM_>>>(xnf, wf16, (float*)d_out, T_, VOCAB_, DIM_);
}

// round 14
// speedup vs baseline: 1.0238x; 1.0238x over previous
#include <cuda_runtime.h>
#include <cuda_bf16.h>
#include <cuda_fp16.h>
#include <math.h>
#include <stdint.h>

// ---------------------------------------------------------------------------
// Model constants
// ---------------------------------------------------------------------------
#define B_      2
#define S_      2048
#define T_      (B_ * S_)        // 4096 tokens
#define DIM_    1024
#define NH_     16
#define HD_     64
#define NL_     4
#define HFF_    2816
#define VOCAB_  32000
#define DD_     (DIM_ * DIM_)
#define FD_     (HFF_ * DIM_)

// bf16 weight arena offsets; QKV fused [wq;wk;wv]/layer, W13 fused [w1;w3]
#define OFF_QKV 0
#define OFF_WO  (NL_ * 3 * DD_)
#define OFF_W13 (OFF_WO + NL_ * DD_)
#define OFF_W2  (OFF_W13 + NL_ * 2 * FD_)
#define WBF_    (OFF_W2 + NL_ * FD_)
#define SZ_OW   (VOCAB_ * DIM_)

// ---------------------------------------------------------------------------
// Scratch
// ---------------------------------------------------------------------------
__device__ __align__(16) float    g_h  [T_ * DIM_];
__device__ __align__(16) float    g_qkv[T_ * 3 * DIM_];
__device__ __align__(16) float    g_g13[T_ * 2 * HFF_];
__device__ __align__(16) uint16_t g_xn_h[T_ * DIM_], g_xn_l[T_ * DIM_];
__device__ __align__(16) uint16_t g_o_h [T_ * DIM_], g_o_l [T_ * DIM_];
__device__ __align__(16) uint16_t g_gg_h[T_ * HFF_], g_gg_l[T_ * HFF_];
__device__ __align__(16) uint16_t g_qp_h[T_ * DIM_], g_qp_l[T_ * DIM_];
__device__ __align__(16) uint16_t g_kp_h[T_ * DIM_], g_kp_l[T_ * DIM_];
__device__ __align__(16) uint16_t g_vp_h[T_ * DIM_], g_vp_l[T_ * DIM_];
__device__ __align__(16) uint16_t g_w_h[WBF_], g_w_l[WBF_];
__device__ __align__(16) uint16_t g_wf16[SZ_OW];
__device__ __align__(16) uint16_t g_xnf16[T_ * DIM_];

// ---------------------------------------------------------------------------
// helpers
// ---------------------------------------------------------------------------
__device__ __forceinline__ uint32_t pack_bf16(__nv_bfloat16 a, __nv_bfloat16 b) {
    return (uint32_t)__bfloat16_as_ushort(a) |
           ((uint32_t)__bfloat16_as_ushort(b) << 16);
}
__device__ __forceinline__ uint32_t pack2f(float a, float b) {
    return pack_bf16(__float2bfloat16(a), __float2bfloat16(b));
}
__device__ __forceinline__ uint32_t pack2f_lo(float a, float b) {
    float ha = __bfloat162float(__float2bfloat16(a));
    float hb = __bfloat162float(__float2bfloat16(b));
    return pack_bf16(__float2bfloat16(a - ha), __float2bfloat16(b - hb));
}
__device__ __forceinline__ uint32_t pack2h(float a, float b) {
    __half2 h = __floats2half2_rn(a, b);
    return *(uint32_t*)&h;
}
__device__ __forceinline__ void split4(float4 v, uint2& hi, uint2& lo) {
    hi.x = pack2f(v.x, v.y);    hi.y = pack2f(v.z, v.w);
    lo.x = pack2f_lo(v.x, v.y); lo.y = pack2f_lo(v.z, v.w);
}
__device__ __forceinline__ void mma_bf16(float* c, const uint32_t* a,
                                         uint32_t b0, uint32_t b1) {
    asm volatile(
        "mma.sync.aligned.m16n8k16.row.col.f32.bf16.bf16.f32 "
        "{%0,%1,%2,%3}, {%4,%5,%6,%7}, {%8,%9}, {%0,%1,%2,%3};"
        : "+f"(c[0]), "+f"(c[1]), "+f"(c[2]), "+f"(c[3])
        : "r"(a[0]), "r"(a[1]), "r"(a[2]), "r"(a[3]),
          "r"(b0), "r"(b1));
}
__device__ __forceinline__ void mma_f16(float* c, const uint32_t* a,
                                        uint32_t b0, uint32_t b1) {
    asm volatile(
        "mma.sync.aligned.m16n8k16.row.col.f32.f16.f16.f32 "
        "{%0,%1,%2,%3}, {%4,%5,%6,%7}, {%8,%9}, {%0,%1,%2,%3};"
        : "+f"(c[0]), "+f"(c[1]), "+f"(c[2]), "+f"(c[3])
        : "r"(a[0]), "r"(a[1]), "r"(a[2]), "r"(a[3]),
          "r"(b0), "r"(b1));
}
__device__ __forceinline__ void ldsm4(uint32_t& r0, uint32_t& r1,
                                      uint32_t& r2, uint32_t& r3, uint32_t addr) {
    asm volatile("ldmatrix.sync.aligned.m8n8.x4.shared.b16 {%0,%1,%2,%3}, [%4];"
        : "=r"(r0), "=r"(r1), "=r"(r2), "=r"(r3) : "r"(addr));
}
__device__ __forceinline__ void ldsm4t(uint32_t& r0, uint32_t& r1,
                                       uint32_t& r2, uint32_t& r3, uint32_t addr) {
    asm volatile("ldmatrix.sync.aligned.m8n8.x4.trans.shared.b16 {%0,%1,%2,%3}, [%4];"
        : "=r"(r0), "=r"(r1), "=r"(r2), "=r"(r3) : "r"(addr));
}
__device__ __forceinline__ void cp16(uint32_t dst, const void* src) {
    asm volatile("cp.async.cg.shared.global [%0], [%1], 16;"
                 :: "r"(dst), "l"(src) : "memory");
}
__device__ __forceinline__ void cp_commit() {
    asm volatile("cp.async.commit_group;" ::: "memory");
}
template<int N>
__device__ __forceinline__ void cp_wait() {
    asm volatile("cp.async.wait_group %0;" :: "n"(N) : "memory");
}

// ---------------------------------------------------------------------------
// Embedding gather
// ---------------------------------------------------------------------------
__global__ void embed_kernel(const int* __restrict__ tokens,
                             const float* __restrict__ emb,
                             float* __restrict__ h) {
    int t = blockIdx.x;
    int tok = tokens[t];
    const float* src = emb + (size_t)tok * DIM_;
    float* dst = h + (size_t)t * DIM_;
    for (int i = threadIdx.x; i < DIM_; i += blockDim.x) dst[i] = src[i];
}

// ---------------------------------------------------------------------------
// weight splits
// ---------------------------------------------------------------------------
__global__ void split_kernel(const float* __restrict__ src,
                             uint16_t* __restrict__ hi,
                             uint16_t* __restrict__ lo, int nquad) {
    int i = blockIdx.x * blockDim.x + threadIdx.x;
    if (i >= nquad) return;
    float4 v = *(const float4*)(src + 4 * (size_t)i);
    uint2 h, l;
    split4(v, h, l);
    *(uint2*)((uint32_t*)hi + 2 * (size_t)i) = h;
    *(uint2*)((uint32_t*)lo + 2 * (size_t)i) = l;
}

__global__ void split_qkv_kernel(const float* __restrict__ wq,
                                 const float* __restrict__ wk,
                                 const float* __restrict__ wv,
                                 uint16_t* __restrict__ hi,
                                 uint16_t* __restrict__ lo) {
    const int QL = 3 * DD_ / 4;
    const int QD = DD_ / 4;
    int i = blockIdx.x * blockDim.x + threadIdx.x;
    int l = i / QL;
    int rem = i - l * QL;
    int part = rem / QD;
    int j = rem - part * QD;
    const float* src = (part == 0 ? wq : part == 1 ? wk : wv) + (size_t)l * DD_ + 4 * (size_t)j;
    float4 v = *(const float4*)src;
    uint2 h, lw;
    split4(v, h, lw);
    *(uint2*)((uint32_t*)hi + 2 * (size_t)i) = h;
    *(uint2*)((uint32_t*)lo + 2 * (size_t)i) = lw;
}

__global__ void split_w13_kernel(const float* __restrict__ w1,
                                 const float* __restrict__ w3,
                                 uint16_t* __restrict__ hi,
                                 uint16_t* __restrict__ lo) {
    const int QL = 2 * FD_ / 4;
    const int QF = FD_ / 4;
    int i = blockIdx.x * blockDim.x + threadIdx.x;
    int l = i / QL;
    int rem = i - l * QL;
    int part = rem / QF;
    int j = rem - part * QF;
    const float* src = (part == 0 ? w1 : w3) + (size_t)l * FD_ + 4 * (size_t)j;
    float4 v = *(const float4*)src;
    uint2 h, lw;
    split4(v, h, lw);
    *(uint2*)((uint32_t*)hi + 2 * (size_t)i) = h;
    *(uint2*)((uint32_t*)lo + 2 * (size_t)i) = lw;
}

__global__ void split_f16_kernel(const float* __restrict__ src,
                                 uint16_t* __restrict__ dst, int nquad) {
    int i = blockIdx.x * blockDim.x + threadIdx.x;
    if (i >= nquad) return;
    float4 v = *(const float4*)(src + 4 * (size_t)i);
    uint2 h;
    h.x = pack2h(v.x, v.y);
    h.y = pack2h(v.z, v.w);
    *(uint2*)((uint32_t*)dst + 2 * (size_t)i) = h;
}

// ---------------------------------------------------------------------------
// RMSNorm -> bf16 hi/lo planes  /  fp16 plane
// ---------------------------------------------------------------------------
__global__ void rmsnorm_split(const float* __restrict__ x,
                              const float* __restrict__ w,
                              uint16_t* __restrict__ yh,
                              uint16_t* __restrict__ yl) {
    int t = blockIdx.x;
    const float* xr = x + (size_t)t * DIM_;
    float ss = 0.f;
    #pragma unroll
    for (int i = threadIdx.x; i < DIM_; i += 256) { float v = xr[i]; ss += v * v; }
    #pragma unroll
    for (int off = 16; off > 0; off >>= 1)
        ss += __shfl_xor_sync(0xffffffffu, ss, off);
    __shared__ float red[8];
    if ((threadIdx.x & 31) == 0) red[threadIdx.x >> 5] = ss;
    __syncthreads();
    float tot = 0.f;
    #pragma unroll
    for (int i = 0; i < 8; i++) tot += red[i];
    float sc = rsqrtf(tot * (1.0f / DIM_) + 1e-5f);
    uint32_t* oh = (uint32_t*)(yh + (size_t)t * DIM_);
    uint32_t* ol = (uint32_t*)(yl + (size_t)t * DIM_);
    #pragma unroll
    for (int i = threadIdx.x * 2; i < DIM_; i += 512) {
        float a = xr[i] * sc * w[i];
        float b = xr[i + 1] * sc * w[i + 1];
        oh[i >> 1] = pack2f(a, b);
        ol[i >> 1] = pack2f_lo(a, b);
    }
}

__global__ void rmsnorm_f16(const float* __restrict__ x,
                            const float* __restrict__ w,
                            uint16_t* __restrict__ y) {
    int t = blockIdx.x;
    const float* xr = x + (size_t)t * DIM_;
    float ss = 0.f;
    #pragma unroll
    for (int i = threadIdx.x; i < DIM_; i += 256) { float v = xr[i]; ss += v * v; }
    #pragma unroll
    for (int off = 16; off > 0; off >>= 1)
        ss += __shfl_xor_sync(0xffffffffu, ss, off);
    __shared__ float red[8];
    if ((threadIdx.x & 31) == 0) red[threadIdx.x >> 5] = ss;
    __syncthreads();
    float tot = 0.f;
    #pragma unroll
    for (int i = 0; i < 8; i++) tot += red[i];
    float sc = rsqrtf(tot * (1.0f / DIM_) + 1e-5f);
    uint32_t* oy = (uint32_t*)(y + (size_t)t * DIM_);
    #pragma unroll
    for (int i = threadIdx.x * 2; i < DIM_; i += 512)
        oy[i >> 1] = pack2h(xr[i] * sc * w[i], xr[i + 1] * sc * w[i + 1]);
}

// ---------------------------------------------------------------------------
// 3xBF16 GEMM NT (R12, proven): 128x128 CTA, 4 warps 64x64, 4-stage pipeline
// ---------------------------------------------------------------------------
#define SW_   12
#define PLW_  (128 * SW_)
#define PLB_  (PLW_ * 4)
#define STGB_ (4 * PLB_)
#define GSM_  (4 * STGB_)

template<bool ACC>
__global__ __launch_bounds__(128, 2)
void tgemm_bb(const uint16_t* __restrict__ Ah, const uint16_t* __restrict__ Al,
              const uint16_t* __restrict__ Bh, const uint16_t* __restrict__ Bl,
              float* __restrict__ C, int M, int N, int K) {
    extern __shared__ __align__(16) uint32_t sm[];

    int tid  = threadIdx.x;
    int m0   = blockIdx.y * 128;
    int n0   = blockIdx.x * 128;
    int wid  = tid >> 5;
    int lane = tid & 31;
    int wm = (wid >> 1) * 64;
    int wn = (wid & 1) * 64;
    int lr = lane >> 2;
    int lc = lane & 3;

    uint32_t smb = (uint32_t)__cvta_generic_to_shared(sm);

    uint32_t aoff[4];
    #pragma unroll
    for (int mf = 0; mf < 4; mf++) {
        int row = wm + mf * 16 + (lane & 7) + ((lane >> 3) & 1) * 8;
        aoff[mf] = row * (SW_ * 4) + (lane >> 4) * 16;
    }
    uint32_t boff[4];
    #pragma unroll
    for (int nfp = 0; nfp < 4; nfp++) {
        int row = wn + nfp * 16 + (lane & 7) + (lane >> 4) * 8;
        boff[nfp] = row * (SW_ * 4) + ((lane >> 3) & 1) * 16;
    }

    int r0 = tid >> 1, h0 = tid & 1;
    int c1 = tid + 128;
    int r1 = c1 >> 1, h1 = c1 & 1;
    uint32_t sd0 = r0 * (SW_ * 4) + h0 * 16;
    uint32_t sd1 = r1 * (SW_ * 4) + h1 * 16;
    size_t ga0 = (size_t)(m0 + r0) * K + h0 * 8;
    size_t ga1 = (size_t)(m0 + r1) * K + h1 * 8;
    size_t gb0 = (size_t)(n0 + r0) * K + h0 * 8;
    size_t gb1 = (size_t)(n0 + r1) * K + h1 * 8;

    auto issue = [&](int bi, int k0) {
        uint32_t sb = smb + (uint32_t)bi * STGB_;
        cp16(sb + 0 * PLB_ + sd0, Ah + ga0 + k0);
        cp16(sb + 0 * PLB_ + sd1, Ah + ga1 + k0);
        cp16(sb + 1 * PLB_ + sd0, Al + ga0 + k0);
        cp16(sb + 1 * PLB_ + sd1, Al + ga1 + k0);
        cp16(sb + 2 * PLB_ + sd0, Bh + gb0 + k0);
        cp16(sb + 2 * PLB_ + sd1, Bh + gb1 + k0);
        cp16(sb + 3 * PLB_ + sd0, Bl + gb0 + k0);
        cp16(sb + 3 * PLB_ + sd1, Bl + gb1 + k0);
        cp_commit();
    };

    float acc[4][8][4];
    #pragma unroll
    for (int i = 0; i < 4; i++)
        #pragma unroll
        for (int j = 0; j < 8; j++)
            #pragma unroll
            for (int t = 0; t < 4; t++) acc[i][j][t] = 0.f;

    int nstage = K >> 4;
    issue(0, 0);
    if (nstage > 1) issue(1, 16);
    if (nstage > 2) issue(2, 32);

    for (int s = 0; s < nstage; s++) {
        int rem = nstage - 1 - s;
        if (rem >= 2)      cp_wait<2>();
        else if (rem == 1) cp_wait<1>();
        else               cp_wait<0>();
        __syncthreads();

        uint32_t bb = smb + (uint32_t)(s & 3) * STGB_;
        uint32_t ah[4][4], al[4][4];
        #pragma unroll
        for (int mf = 0; mf < 4; mf++) {
            ldsm4(ah[mf][0], ah[mf][1], ah[mf][2], ah[mf][3], bb + aoff[mf]);
            ldsm4(al[mf][0], al[mf][1], al[mf][2], al[mf][3], bb + PLB_ + aoff[mf]);
        }
        #pragma unroll
        for (int g = 0; g < 2; g++) {
            uint32_t bh[2][4], bl[2][4];
            #pragma unroll
            for (int p = 0; p < 2; p++) {
                int nfp = g * 2 + p;
                ldsm4(bh[p][0], bh[p][1], bh[p][2], bh[p][3],
                      bb + 2 * PLB_ + boff[nfp]);
                ldsm4(bl[p][0], bl[p][1], bl[p][2], bl[p][3],
                      bb + 3 * PLB_ + boff[nfp]);
            }
            #pragma unroll
            for (int p = 0; p < 2; p++) {
                int nf0 = (g * 2 + p) * 2, nf1 = nf0 + 1;
                #pragma unroll
                for (int mf = 0; mf < 4; mf++) {
                    mma_bf16(acc[mf][nf0], al[mf], bh[p][0], bh[p][1]);
                    mma_bf16(acc[mf][nf1], al[mf], bh[p][2], bh[p][3]);
                }
            }
            #pragma unroll
            for (int p = 0; p < 2; p++) {
                int nf0 = (g * 2 + p) * 2, nf1 = nf0 + 1;
                #pragma unroll
                for (int mf = 0; mf < 4; mf++) {
                    mma_bf16(acc[mf][nf0], ah[mf], bl[p][0], bl[p][1]);
                    mma_bf16(acc[mf][nf1], ah[mf], bl[p][2], bl[p][3]);
                }
            }
            #pragma unroll
            for (int p = 0; p < 2; p++) {
                int nf0 = (g * 2 + p) * 2, nf1 = nf0 + 1;
                #pragma unroll
                for (int mf = 0; mf < 4; mf++) {
                    mma_bf16(acc[mf][nf0], ah[mf], bh[p][0], bh[p][1]);
                    mma_bf16(acc[mf][nf1], ah[mf], bh[p][2], bh[p][3]);
                }
            }
        }

        int ns = s + 3;
        if (ns < nstage) issue(ns & 3, ns * 16);
    }

    #pragma unroll
    for (int mf = 0; mf < 4; mf++) {
        #pragma unroll
        for (int nf = 0; nf < 8; nf++) {
            int row = m0 + wm + mf * 16 + lr;
            int col = n0 + wn + nf * 8 + 2 * lc;
            float* p0 = C + (size_t)row * N + col;
            float* p1 = p0 + (size_t)8 * N;
            if (ACC) {
                float2 u0 = *(float2*)p0;
                float2 u1 = *(float2*)p1;
                u0.x += acc[mf][nf][0]; u0.y += acc[mf][nf][1];
                u1.x += acc[mf][nf][2]; u1.y += acc[mf][nf][3];
                *(float2*)p0 = u0;
                *(float2*)p1 = u1;
            } else {
                *(float2*)p0 = make_float2(acc[mf][nf][0], acc[mf][nf][1]);
                *(float2*)p1 = make_float2(acc[mf][nf][2], acc[mf][nf][3]);
            }
        }
    }
}

// ---------------------------------------------------------------------------
// fp16 single-pass GEMM NT (logits), 4 warps 64x64 warp tile (crossbar fix)
// ---------------------------------------------------------------------------
#define HSTGB_ (2 * PLB_)
#define HGSM_  (4 * HSTGB_)

__global__ __launch_bounds__(128, 2)
void tgemm_hh(const uint16_t* __restrict__ A, const uint16_t* __restrict__ B,
              float* __restrict__ C, int M, int N, int K) {
    extern __shared__ __align__(16) uint32_t sm[];

    int tid  = threadIdx.x;
    int m0   = blockIdx.y * 128;
    int n0   = blockIdx.x * 128;
    int wid  = tid >> 5;
    int lane = tid & 31;
    int wm = (wid >> 1) * 64;
    int wn = (wid & 1) * 64;
    int lr = lane >> 2;
    int lc = lane & 3;

    uint32_t smb = (uint32_t)__cvta_generic_to_shared(sm);

    uint32_t aoff[4];
    #pragma unroll
    for (int mf = 0; mf < 4; mf++) {
        int row = wm + mf * 16 + (lane & 7) + ((lane >> 3) & 1) * 8;
        aoff[mf] = row * (SW_ * 4) + (lane >> 4) * 16;
    }
    uint32_t boff[4];
    #pragma unroll
    for (int nfp = 0; nfp < 4; nfp++) {
        int row = wn + nfp * 16 + (lane & 7) + (lane >> 4) * 8;
        boff[nfp] = row * (SW_ * 4) + ((lane >> 3) & 1) * 16;
    }

    int r0 = tid >> 1, h0 = tid & 1;
    int c1 = tid + 128;
    int r1 = c1 >> 1, h1 = c1 & 1;
    uint32_t sd0 = r0 * (SW_ * 4) + h0 * 16;
    uint32_t sd1 = r1 * (SW_ * 4) + h1 * 16;
    size_t ga0 = (size_t)(m0 + r0) * K + h0 * 8;
    size_t ga1 = (size_t)(m0 + r1) * K + h1 * 8;
    size_t gb0 = (size_t)(n0 + r0) * K + h0 * 8;
    size_t gb1 = (size_t)(n0 + r1) * K + h1 * 8;

    auto issue = [&](int bi, int k0) {
        uint32_t sb = smb + (uint32_t)bi * HSTGB_;
        cp16(sb + sd0, A + ga0 + k0);
        cp16(sb + sd1, A + ga1 + k0);
        cp16(sb + PLB_ + sd0, B + gb0 + k0);
        cp16(sb + PLB_ + sd1, B + gb1 + k0);
        cp_commit();
    };

    float acc[4][8][4];
    #pragma unroll
    for (int i = 0; i < 4; i++)
        #pragma unroll
        for (int j = 0; j < 8; j++)
            #pragma unroll
            for (int t = 0; t < 4; t++) acc[i][j][t] = 0.f;

    int nstage = K >> 4;
    issue(0, 0);
    if (nstage > 1) issue(1, 16);
    if (nstage > 2) issue(2, 32);

    for (int s = 0; s < nstage; s++) {
        int rem = nstage - 1 - s;
        if (rem >= 2)      cp_wait<2>();
        else if (rem == 1) cp_wait<1>();
        else               cp_wait<0>();
        __syncthreads();

        uint32_t bb = smb + (uint32_t)(s & 3) * HSTGB_;
        uint32_t a[4][4];
        #pragma unroll
        for (int mf = 0; mf < 4; mf++)
            ldsm4(a[mf][0], a[mf][1], a[mf][2], a[mf][3], bb + aoff[mf]);
        #pragma unroll
        for (int nfp = 0; nfp < 4; nfp++) {
            uint32_t bh[4];
            ldsm4(bh[0], bh[1], bh[2], bh[3], bb + PLB_ + boff[nfp]);
            int nf0 = nfp * 2, nf1 = nf0 + 1;
            #pragma unroll
            for (int mf = 0; mf < 4; mf++) {
                mma_f16(acc[mf][nf0], a[mf], bh[0], bh[1]);
                mma_f16(acc[mf][nf1], a[mf], bh[2], bh[3]);
            }
        }

        int ns = s + 3;
        if (ns < nstage) issue(ns & 3, ns * 16);
    }

    #pragma unroll
    for (int mf = 0; mf < 4; mf++) {
        #pragma unroll
        for (int nf = 0; nf < 8; nf++) {
            int row = m0 + wm + mf * 16 + lr;
            int col = n0 + wn + nf * 8 + 2 * lc;
            float* p0 = C + (size_t)row * N + col;
            float* p1 = p0 + (size_t)8 * N;
            *(float2*)p0 = make_float2(acc[mf][nf][0], acc[mf][nf][1]);
            *(float2*)p1 = make_float2(acc[mf][nf][2], acc[mf][nf][3]);
        }
    }
}

// ---------------------------------------------------------------------------
// RoPE + split (fused qkv -> q/k/v bf16 hi/lo planes; q pre-scaled 1/8)
// ---------------------------------------------------------------------------
__global__ void rope_split_kernel(const float* __restrict__ qkv,
                                  uint16_t* __restrict__ qh, uint16_t* __restrict__ ql,
                                  uint16_t* __restrict__ kh, uint16_t* __restrict__ kl,
                                  uint16_t* __restrict__ vh, uint16_t* __restrict__ vl) {
    int idx = blockIdx.x * blockDim.x + threadIdx.x;
    int t = idx >> 9;
    int p = idx & 511;
    int i = p & 31;
    int s = t & (S_ - 1);
    float inv = expf(-(float)(2 * i) * (1.0f / HD_) * 9.210340371976184f);
    float ang = (float)s * inv;
    float sn, cs;
    sincosf(ang, &sn, &cs);

    const float* row = qkv + (size_t)t * (3 * DIM_);
    float q0 = row[2 * p],        q1 = row[2 * p + 1];
    float k0 = row[DIM_ + 2 * p], k1 = row[DIM_ + 2 * p + 1];
    float v0 = row[2 * DIM_ + 2 * p], v1 = row[2 * DIM_ + 2 * p + 1];

    float qr0 = (q0 * cs - q1 * sn) * 0.125f;
    float qr1 = (q0 * sn + q1 * cs) * 0.125f;
    float kr0 = k0 * cs - k1 * sn;
    float kr1 = k0 * sn + k1 * cs;

    uint32_t w = (uint32_t)t * 512 + p;
    ((uint32_t*)qh)[w] = pack2f(qr0, qr1);
    ((uint32_t*)ql)[w] = pack2f_lo(qr0, qr1);
    ((uint32_t*)kh)[w] = pack2f(kr0, kr1);
    ((uint32_t*)kl)[w] = pack2f_lo(kr0, kr1);
    ((uint32_t*)vh)[w] = pack2f(v0, v1);
    ((uint32_t*)vl)[w] = pack2f_lo(v0, v1);
}

// ---------------------------------------------------------------------------
// Tensor-core flash attention on pre-split bf16 planes (R10, proven)
// ---------------------------------------------------------------------------
#define APW_ 36
#define APLB_ (64 * APW_ * 4)

__global__ __launch_bounds__(128)
void attn_mma_kernel(const uint16_t* __restrict__ qh, const uint16_t* __restrict__ ql,
                     const uint16_t* __restrict__ kh, const uint16_t* __restrict__ kl,
                     const uint16_t* __restrict__ vh, const uint16_t* __restrict__ vl,
                     uint16_t* __restrict__ oh, uint16_t* __restrict__ ol) {
    __shared__ __align__(16) uint32_t sK[2][64 * APW_];
    __shared__ __align__(16) uint32_t sV[2][64 * APW_];

    int q0  = blockIdx.x * 64;
    int h   = blockIdx.y;
    int b   = blockIdx.z;
    int tid = threadIdx.x;
    int w   = tid >> 5;
    int lane = tid & 31;
    int lr = lane >> 2, lc = lane & 3;

    size_t base = ((size_t)b * S_) * DIM_ + (size_t)h * HD_;

    uint32_t sKb = (uint32_t)__cvta_generic_to_shared(&sK[0][0]);
    uint32_t sVb = (uint32_t)__cvta_generic_to_shared(&sV[0][0]);

    #pragma unroll
    for (int i = 0; i < 8; i++) {
        int idx = tid + i * 128;
        int row = idx >> 4, c4 = idx & 15;
        size_t e = base + (size_t)(q0 + row) * DIM_ + c4 * 4;
        uint32_t wofs = (uint32_t)(e >> 1);
        int wo = row * APW_ + c4 * 2;
        *(uint2*)&sK[0][wo] = *(const uint2*)((const uint32_t*)qh + wofs);
        *(uint2*)&sK[1][wo] = *(const uint2*)((const uint32_t*)ql + wofs);
    }
    __syncthreads();

    uint32_t Qh[4][4], Ql[4][4];
    {
        int arow = w * 16 + (lane & 7) + ((lane >> 3) & 1) * 8;
        uint32_t ab = arow * (APW_ * 4) + (lane >> 4) * 16;
        #pragma unroll
        for (int kc = 0; kc < 4; kc++) {
            ldsm4(Qh[kc][0], Qh[kc][1], Qh[kc][2], Qh[kc][3], sKb + ab + kc * 32);
            ldsm4(Ql[kc][0], Ql[kc][1], Ql[kc][2], Ql[kc][3], sKb + APLB_ + ab + kc * 32);
        }
    }

    uint32_t koff[4], voff[4][4];
    #pragma unroll
    for (int nfp = 0; nfp < 4; nfp++) {
        int row = nfp * 16 + (lane & 7) + (lane >> 4) * 8;
        koff[nfp] = row * (APW_ * 4) + ((lane >> 3) & 1) * 16;
        #pragma unroll
        for (int kc = 0; kc < 4; kc++) {
            int vrow = kc * 16 + ((lane >> 3) & 1) * 8 + (lane & 7);
            voff[nfp][kc] = vrow * (APW_ * 4) + (nfp * 2 + (lane >> 4)) * 16;
        }
    }

    float accO[8][4];
    #pragma unroll
    for (int nf = 0; nf < 8; nf++)
        #pragma unroll
        for (int t = 0; t < 4; t++) accO[nf][t] = 0.f;
    float m0 = -INFINITY, m1 = -INFINITY, l0 = 0.f, l1 = 0.f;

    int nkt = blockIdx.x + 1;
    for (int kt = 0; kt < nkt; kt++) {
        int k0 = kt * 64;
        __syncthreads();
        #pragma unroll
        for (int i = 0; i < 8; i++) {
            int idx = tid + i * 128;
            int row = idx >> 4, c4 = idx & 15;
            size_t e = base + (size_t)(k0 + row) * DIM_ + c4 * 4;
            uint32_t wofs = (uint32_t)(e >> 1);
            int wo = row * APW_ + c4 * 2;
            *(uint2*)&sK[0][wo] = *(const uint2*)((const uint32_t*)kh + wofs);
            *(uint2*)&sK[1][wo] = *(const uint2*)((const uint32_t*)kl + wofs);
            *(uint2*)&sV[0][wo] = *(const uint2*)((const uint32_t*)vh + wofs);
            *(uint2*)&sV[1][wo] = *(const uint2*)((const uint32_t*)vl + wofs);
        }
        __syncthreads();

        float sc[8][4];
        #pragma unroll
        for (int nf = 0; nf < 8; nf++)
            #pragma unroll
            for (int t = 0; t < 4; t++) sc[nf][t] = 0.f;

        #pragma unroll
        for (int nfp = 0; nfp < 4; nfp++) {
            #pragma unroll
            for (int kc = 0; kc < 4; kc++) {
                uint32_t bh[4], bl[4];
                ldsm4(bh[0], bh[1], bh[2], bh[3], sKb + koff[nfp] + kc * 32);
                ldsm4(bl[0], bl[1], bl[2], bl[3], sKb + APLB_ + koff[nfp] + kc * 32);
                int nf0 = nfp * 2, nf1 = nf0 + 1;
                mma_bf16(sc[nf0], Ql[kc], bh[0], bh[1]);
                mma_bf16(sc[nf0], Qh[kc], bl[0], bl[1]);
                mma_bf16(sc[nf0], Qh[kc], bh[0], bh[1]);
                mma_bf16(sc[nf1], Ql[kc], bh[2], bh[3]);
                mma_bf16(sc[nf1], Qh[kc], bl[2], bl[3]);
                mma_bf16(sc[nf1], Qh[kc], bh[2], bh[3]);
            }
        }

        if (kt == nkt - 1) {
            int row0 = w * 16 + lr;
            int row1 = row0 + 8;
            #pragma unroll
            for (int nf = 0; nf < 8; nf++) {
                int col = nf * 8 + 2 * lc;
                if (col     > row0) sc[nf][0] = -INFINITY;
                if (col + 1 > row0) sc[nf][1] = -INFINITY;
                if (col     > row1) sc[nf][2] = -INFINITY;
                if (col + 1 > row1) sc[nf][3] = -INFINITY;
            }
        }

        float tm0 = -INFINITY, tm1 = -INFINITY;
        #pragma unroll
        for (int nf = 0; nf < 8; nf++) {
            tm0 = fmaxf(tm0, fmaxf(sc[nf][0], sc[nf][1]));
            tm1 = fmaxf(tm1, fmaxf(sc[nf][2], sc[nf][3]));
        }
        #pragma unroll
        for (int off = 1; off < 4; off <<= 1) {
            tm0 = fmaxf(tm0, __shfl_xor_sync(0xffffffffu, tm0, off));
            tm1 = fmaxf(tm1, __shfl_xor_sync(0xffffffffu, tm1, off));
        }
        float mn0 = fmaxf(m0, tm0), mn1 = fmaxf(m1, tm1);
        float corr0 = __expf(m0 - mn0), corr1 = __expf(m1 - mn1);
        m0 = mn0; m1 = mn1;

        float ls0 = 0.f, ls1 = 0.f;
        #pragma unroll
        for (int nf = 0; nf < 8; nf++) {
            sc[nf][0] = __expf(sc[nf][0] - mn0);
            sc[nf][1] = __expf(sc[nf][1] - mn0);
            sc[nf][2] = __expf(sc[nf][2] - mn1);
            sc[nf][3] = __expf(sc[nf][3] - mn1);
            ls0 += sc[nf][0] + sc[nf][1];
            ls1 += sc[nf][2] + sc[nf][3];
        }
        #pragma unroll
        for (int off = 1; off < 4; off <<= 1) {
            ls0 += __shfl_xor_sync(0xffffffffu, ls0, off);
            ls1 += __shfl_xor_sync(0xffffffffu, ls1, off);
        }
        l0 = l0 * corr0 + ls0;
        l1 = l1 * corr1 + ls1;
        #pragma unroll
        for (int nf = 0; nf < 8; nf++) {
            accO[nf][0] *= corr0; accO[nf][1] *= corr0;
            accO[nf][2] *= corr1; accO[nf][3] *= corr1;
        }

        uint32_t Ph[4][4], Pl[4][4];
        #pragma unroll
        for (int kc = 0; kc < 4; kc++) {
            int na = 2 * kc, nb = 2 * kc + 1;
            Ph[kc][0] = pack2f(sc[na][0], sc[na][1]);
            Ph[kc][1] = pack2f(sc[na][2], sc[na][3]);
            Ph[kc][2] = pack2f(sc[nb][0], sc[nb][1]);
            Ph[kc][3] = pack2f(sc[nb][2], sc[nb][3]);
            Pl[kc][0] = pack2f_lo(sc[na][0], sc[na][1]);
            Pl[kc][1] = pack2f_lo(sc[na][2], sc[na][3]);
            Pl[kc][2] = pack2f_lo(sc[nb][0], sc[nb][1]);
            Pl[kc][3] = pack2f_lo(sc[nb][2], sc[nb][3]);
        }

        #pragma unroll
        for (int nfp = 0; nfp < 4; nfp++) {
            #pragma unroll
            for (int kc = 0; kc < 4; kc++) {
                uint32_t vhf[4], vlf[4];
                ldsm4t(vhf[0], vhf[1], vhf[2], vhf[3], sVb + voff[nfp][kc]);
                ldsm4t(vlf[0], vlf[1], vlf[2], vlf[3], sVb + APLB_ + voff[nfp][kc]);
                int nf0 = nfp * 2, nf1 = nf0 + 1;
                mma_bf16(accO[nf0], Pl[kc], vhf[0], vhf[1]);
                mma_bf16(accO[nf0], Ph[kc], vlf[0], vlf[1]);
                mma_bf16(accO[nf0], Ph[kc], vhf[0], vhf[1]);
                mma_bf16(accO[nf1], Pl[kc], vhf[2], vhf[3]);
                mma_bf16(accO[nf1], Ph[kc], vlf[2], vlf[3]);
                mma_bf16(accO[nf1], Ph[kc], vhf[2], vhf[3]);
            }
        }
    }

    float inv0 = 1.f / l0, inv1 = 1.f / l1;
    int row0 = q0 + w * 16 + lr;
    #pragma unroll
    for (int nf = 0; nf < 8; nf++) {
        int col = nf * 8 + 2 * lc;
        float x0 = accO[nf][0] * inv0, x1 = accO[nf][1] * inv0;
        float y0 = accO[nf][2] * inv1, y1 = accO[nf][3] * inv1;
        size_t e0 = base + (size_t)row0 * DIM_ + col;
        size_t e1 = base + (size_t)(row0 + 8) * DIM_ + col;
        *(uint32_t*)(oh + e0) = pack2f(x0, x1);
        *(uint32_t*)(ol + e0) = pack2f_lo(x0, x1);
        *(uint32_t*)(oh + e1) = pack2f(y0, y1);
        *(uint32_t*)(ol + e1) = pack2f_lo(y0, y1);
    }
}

// ---------------------------------------------------------------------------
// SwiGLU on fused g13 buffer -> planes
// ---------------------------------------------------------------------------
__global__ void silu_mul_split13(const float* __restrict__ g13,
                                 uint16_t* __restrict__ gh,
                                 uint16_t* __restrict__ gl) {
    int t = blockIdx.x;
    int j = blockIdx.y * 128 + threadIdx.x;
    const float* r = g13 + (size_t)t * (2 * HFF_);
    float2 a = *(const float2*)(r + 2 * j);
    float2 b = *(const float2*)(r + HFF_ + 2 * j);
    float r0 = a.x / (1.f + __expf(-a.x)) * b.x;
    float r1 = a.y / (1.f + __expf(-a.y)) * b.y;
    uint32_t w = (uint32_t)t * (HFF_ / 2) + j;
    ((uint32_t*)gh)[w] = pack2f(r0, r1);
    ((uint32_t*)gl)[w] = pack2f_lo(r0, r1);
}

// ---------------------------------------------------------------------------
// Host orchestration
// ---------------------------------------------------------------------------
extern "C" void kernel_launch(void* const* d_in, const int* in_sizes, int n_in,
                              void* d_out, int out_size) {
    const int*   tokens      = (const int*)  d_in[0];
    const float* tok_emb     = (const float*)d_in[1];
    const float* wq          = (const float*)d_in[2];
    const float* wk          = (const float*)d_in[3];
    const float* wv          = (const float*)d_in[4];
    const float* wo          = (const float*)d_in[5];
    const float* w1          = (const float*)d_in[6];
    const float* w2          = (const float*)d_in[7];
    const float* w3          = (const float*)d_in[8];
    const float* attn_norm_w = (const float*)d_in[9];
    const float* ffn_norm_w  = (const float*)d_in[10];
    const float* norm_w      = (const float*)d_in[11];
    const float* out_w       = (const float*)d_in[12];

    float *h, *qkv, *g13;
    uint16_t *xnh, *xnl, *ooh, *ool, *ggh, *ggl, *wh, *wl, *wf16, *xnf;
    uint16_t *qph, *qpl, *kph, *kpl, *vph, *vpl;
    cudaGetSymbolAddress((void**)&h,    g_h);
    cudaGetSymbolAddress((void**)&qkv,  g_qkv);
    cudaGetSymbolAddress((void**)&g13,  g_g13);
    cudaGetSymbolAddress((void**)&xnh,  g_xn_h);
    cudaGetSymbolAddress((void**)&xnl,  g_xn_l);
    cudaGetSymbolAddress((void**)&ooh,  g_o_h);
    cudaGetSymbolAddress((void**)&ool,  g_o_l);
    cudaGetSymbolAddress((void**)&ggh,  g_gg_h);
    cudaGetSymbolAddress((void**)&ggl,  g_gg_l);
    cudaGetSymbolAddress((void**)&qph,  g_qp_h);
    cudaGetSymbolAddress((void**)&qpl,  g_qp_l);
    cudaGetSymbolAddress((void**)&kph,  g_kp_h);
    cudaGetSymbolAddress((void**)&kpl,  g_kp_l);
    cudaGetSymbolAddress((void**)&vph,  g_vp_h);
    cudaGetSymbolAddress((void**)&vpl,  g_vp_l);
    cudaGetSymbolAddress((void**)&wh,   g_w_h);
    cudaGetSymbolAddress((void**)&wl,   g_w_l);
    cudaGetSymbolAddress((void**)&wf16, g_wf16);
    cudaGetSymbolAddress((void**)&xnf,  g_xnf16);

    cudaFuncSetAttribute(tgemm_bb<false>, cudaFuncAttributeMaxDynamicSharedMemorySize, GSM_);
    cudaFuncSetAttribute(tgemm_bb<true >, cudaFuncAttributeMaxDynamicSharedMemorySize, GSM_);
    cudaFuncSetAttribute(tgemm_hh, cudaFuncAttributeMaxDynamicSharedMemorySize, HGSM_);

    // fused weight pre-splits (5 launches)
    {
        int nq = NL_ * 3 * DD_ / 4;
        split_qkv_kernel<<<nq / 256, 256>>>(wq, wk, wv, wh + OFF_QKV, wl + OFF_QKV);
    }
    {
        int nq = NL_ * 2 * FD_ / 4;
        split_w13_kernel<<<nq / 256, 256>>>(w1, w3, wh + OFF_W13, wl + OFF_W13);
    }
    split_kernel<<<(NL_ * DD_ / 4) / 256, 256>>>(wo, wh + OFF_WO, wl + OFF_WO, NL_ * DD_ / 4);
    split_kernel<<<(NL_ * FD_ / 4) / 256, 256>>>(w2, wh + OFF_W2, wl + OFF_W2, NL_ * FD_ / 4);
    split_f16_kernel<<<(SZ_OW / 4) / 256, 256>>>(out_w, wf16, SZ_OW / 4);

    embed_kernel<<<T_, 256>>>(tokens, tok_emb, h);

    dim3 gQKV(3 * DIM_ / 128, T_ / 128);
    dim3 gDD (DIM_     / 128, T_ / 128);
    dim3 gF13(2 * HFF_ / 128, T_ / 128);
    dim3 gDV (VOCAB_   / 128, T_ / 128);

    for (int l = 0; l < NL_; l++) {
        size_t oQKV = OFF_QKV + (size_t)l * 3 * DD_;
        size_t oWO  = OFF_WO  + (size_t)l * DD_;
        size_t oW13 = OFF_W13 + (size_t)l * 2 * FD_;
        size_t oW2  = OFF_W2  + (size_t)l * FD_;

        rmsnorm_split<<<T_, 256>>>(h, attn_norm_w + (size_t)l * DIM_, xnh, xnl);
        tgemm_bb<false><<<gQKV, 128, GSM_>>>(xnh, xnl, wh + oQKV, wl + oQKV,
                                             qkv, T_, 3 * DIM_, DIM_);
        rope_split_kernel<<<(T_ * 512) / 256, 256>>>(qkv, qph, qpl, kph, kpl, vph, vpl);
        attn_mma_kernel<<<dim3(S_ / 64, NH_, B_), 128>>>(qph, qpl, kph, kpl, vph, vpl,
                                                         ooh, ool);
        tgemm_bb<true ><<<gDD, 128, GSM_>>>(ooh, ool, wh + oWO, wl + oWO,
                                            h, T_, DIM_, DIM_);

        rmsnorm_split<<<T_, 256>>>(h, ffn_norm_w + (size_t)l * DIM_, xnh, xnl);
        tgemm_bb<false><<<gF13, 128, GSM_>>>(xnh, xnl, wh + oW13, wl + oW13,
                                             g13, T_, 2 * HFF_, DIM_);
        silu_mul_split13<<<dim3(T_, HFF_ / 256), 128>>>(g13, ggh, ggl);
        tgemm_bb<true ><<<gDD, 128, GSM_>>>(ggh, ggl, wh + oW2, wl + oW2,
                                            h, T_, DIM_, HFF_);
    }

    rmsnorm_f16<<<T_, 256>>>(h, norm_w, xnf);
    tgemm_hh<<<gDV, 128, HGSM_>>>(xnf, wf16, (float*)d_out, T_, VOCAB_, DIM_);
}